// round 14
// baseline (speedup 1.0000x reference)
#include <cuda_runtime.h>
#include <cstdint>
#include <math.h>

// ---------------- problem constants ----------------
#define DMODEL 1024
#define NHEAD  16
#define DKH    64
#define RNK    256
#define BATCH  4
#define SEQ    2048
#define ROWS   (BATCH * SEQ)                 // 8192
#define ZBH    (BATCH * NHEAD)               // 64
static const long long OUT_ELEMS  = (long long)ROWS * DMODEL;             // 8,388,608
static const long long ATTN_ELEMS = (long long)BATCH * NHEAD * SEQ * SEQ; // 268,435,456

// ---------------- static scratch ----------------
__device__ float g_tmp[ROWS * RNK * 3];      // low-rank intermediates (q,k,v batched)
__device__ float g_qh [ROWS * DMODEL];
__device__ float g_kh [ROWS * DMODEL];
__device__ float g_vh [ROWS * DMODEL];
__device__ float g_ctx[ROWS * DMODEL];
__device__ float g_pre[ROWS * DMODEL];
__device__ float g_attn_scratch[(size_t)BATCH * NHEAD * SEQ * SEQ];

// ---------------- PTX helpers ----------------
__device__ __forceinline__ uint32_t smem_u32(const void* p) {
    uint32_t a;
    asm("{ .reg .u64 t; cvta.to.shared.u64 t, %1; cvt.u32.u64 %0, t; }" : "=r"(a) : "l"(p));
    return a;
}
#define CP16(dst, src) \
    asm volatile("cp.async.cg.shared.global [%0], [%1], 16;" :: "r"(dst), "l"(src))
#define CP_COMMIT() asm volatile("cp.async.commit_group;")
#define CP_WAIT(N)  asm volatile("cp.async.wait_group %0;" :: "n"(N))

__device__ __forceinline__ void mma_tf32(float* c, const uint32_t* a, const uint32_t* b) {
    asm volatile("mma.sync.aligned.m16n8k8.row.col.f32.tf32.tf32.f32 "
                 "{%0,%1,%2,%3}, {%4,%5,%6,%7}, {%8,%9}, {%0,%1,%2,%3};"
                 : "+f"(c[0]), "+f"(c[1]), "+f"(c[2]), "+f"(c[3])
                 : "r"(a[0]), "r"(a[1]), "r"(a[2]), "r"(a[3]),
                   "r"(b[0]), "r"(b[1]));
}
// TF32 multiplicands use the top 19 bits of a b32 register; raw fp32 bits = truncation.
__device__ __forceinline__ uint32_t ftf(float x) { return __float_as_uint(x); }

// ---------------- GEMM body: BM x BN x 16 tile, 8 warps, 3-stage cp.async ----------------
// C[M,N] = alpha * A[M,K] @ op(B) (+ R)
// NMAJOR=true : B is [K,N] row-major ; NMAJOR=false: B is [N,K] row-major (C = A@B^T)
template <int BN, int WM, int WN, bool NMAJOR, bool RES>
__device__ __forceinline__ void gemm_body(
    const float* __restrict__ A, int lda,
    const float* __restrict__ B, int ldb,
    float* __restrict__ C, int ldc,
    const float* __restrict__ R,
    int K, float alpha)
{
    constexpr int BM = 128;
    constexpr int BK = 16;
    constexpr int MT = WM / 16;
    constexpr int NT = WN / 8;
    constexpr int WCOLS = BN / WN;
    constexpr int ASTR = BK + 4;                 // 20 floats
    constexpr int BROWS = NMAJOR ? BK : BN;
    constexpr int BSTR  = NMAJOR ? (BN + 4) : (BK + 4);
    constexpr int ABUF = BM * ASTR;
    constexpr int BBUF = BROWS * BSTR;

    extern __shared__ float dyn[];
    float* Asb = dyn;                            // 3 * ABUF
    float* Bsb = dyn + 3 * ABUF;                 // 3 * BBUF

    const int row0 = blockIdx.y * BM;
    const int col0 = blockIdx.x * BN;
    const int tid = threadIdx.x;
    const int wid = tid >> 5;
    const int lid = tid & 31;
    const int g = lid >> 2;
    const int t = lid & 3;
    const int wr = wid / WCOLS;
    const int wc = wid % WCOLS;
    const int wm0 = wr * WM;
    const int wn0 = wc * WN;

    float acc[MT][NT][4];
    #pragma unroll
    for (int i = 0; i < MT; i++)
        #pragma unroll
        for (int j = 0; j < NT; j++)
            #pragma unroll
            for (int x = 0; x < 4; x++) acc[i][j][x] = 0.f;

    const int KT = K >> 4;

    auto load_tile = [&](int kt, int buf) {
        const int k0 = kt * BK;
        const uint32_t sa  = smem_u32(Asb + buf * ABUF);
        const uint32_t sbm = smem_u32(Bsb + buf * BBUF);
        #pragma unroll
        for (int i = 0; i < (BM * 4) / 256; i++) {
            int idx = tid + i * 256;
            int r = idx >> 2, s = idx & 3;
            CP16(sa + (uint32_t)(r * ASTR + s * 4) * 4,
                 A + (long long)(row0 + r) * lda + k0 + s * 4);
        }
        if constexpr (NMAJOR) {
            #pragma unroll
            for (int i = 0; i < (BK * BN / 4) / 256; i++) {
                int idx = tid + i * 256;
                int r = idx / (BN / 4), s = idx % (BN / 4);
                CP16(sbm + (uint32_t)(r * BSTR + s * 4) * 4,
                     B + (long long)(k0 + r) * ldb + col0 + s * 4);
            }
        } else {
            #pragma unroll
            for (int i = 0; i < (BN * 4) / 256; i++) {
                int idx = tid + i * 256;
                int r = idx >> 2, s = idx & 3;
                CP16(sbm + (uint32_t)(r * BSTR + s * 4) * 4,
                     B + (long long)(col0 + r) * ldb + k0 + s * 4);
            }
        }
        CP_COMMIT();
    };

    // 3-stage pipeline with constant pending-group count (empty commits at tail)
    load_tile(0, 0);
    if (KT > 1) load_tile(1, 1); else CP_COMMIT();

    int buf = 0;
    for (int kt = 0; kt < KT; kt++) {
        if (kt + 2 < KT) load_tile(kt + 2, (buf + 2) % 3); else CP_COMMIT();
        CP_WAIT(2);
        __syncthreads();

        const float* pa = Asb + buf * ABUF;
        const float* pb = Bsb + buf * BBUF;
        #pragma unroll
        for (int ks = 0; ks < 2; ks++) {
            uint32_t af[MT][4];
            uint32_t bf[NT][2];
            #pragma unroll
            for (int mi = 0; mi < MT; mi++) {
                int ar = wm0 + mi * 16 + g;
                int ac = ks * 8 + t;
                af[mi][0] = ftf(pa[ar * ASTR + ac]);
                af[mi][1] = ftf(pa[(ar + 8) * ASTR + ac]);
                af[mi][2] = ftf(pa[ar * ASTR + ac + 4]);
                af[mi][3] = ftf(pa[(ar + 8) * ASTR + ac + 4]);
            }
            #pragma unroll
            for (int ni = 0; ni < NT; ni++) {
                int bn = wn0 + ni * 8 + g;
                int bk = ks * 8 + t;
                if constexpr (NMAJOR) {
                    bf[ni][0] = ftf(pb[bk * BSTR + bn]);
                    bf[ni][1] = ftf(pb[(bk + 4) * BSTR + bn]);
                } else {
                    bf[ni][0] = ftf(pb[bn * BSTR + bk]);
                    bf[ni][1] = ftf(pb[bn * BSTR + bk + 4]);
                }
            }
            #pragma unroll
            for (int mi = 0; mi < MT; mi++)
                #pragma unroll
                for (int ni = 0; ni < NT; ni++)
                    mma_tf32(acc[mi][ni], af[mi], bf[ni]);
        }
        __syncthreads();
        buf = (buf + 1) % 3;
    }

    // ---- epilogue ----
    #pragma unroll
    for (int mi = 0; mi < MT; mi++) {
        #pragma unroll
        for (int ni = 0; ni < NT; ni++) {
            int r0 = row0 + wm0 + mi * 16 + g;
            int c0 = col0 + wn0 + ni * 8 + 2 * t;
            long long i0 = (long long)r0 * ldc + c0;
            long long i1 = i0 + 8LL * ldc;
            float v0 = acc[mi][ni][0] * alpha;
            float v1 = acc[mi][ni][1] * alpha;
            float v2 = acc[mi][ni][2] * alpha;
            float v3 = acc[mi][ni][3] * alpha;
            if constexpr (RES) {
                v0 += R[i0]; v1 += R[i0 + 1];
                v2 += R[i1]; v3 += R[i1 + 1];
            }
            *reinterpret_cast<float2*>(C + i0) = make_float2(v0, v1);
            *reinterpret_cast<float2*>(C + i1) = make_float2(v2, v3);
        }
    }
}

// ---------------- kernel wrappers ----------------
struct GemmPtrs {
    const float* A[3];
    const float* B[3];
    float*       C[3];
};

// batched-triple (q,k,v share shapes): z selects pointer set
template <int BN, int WM, int WN>
__global__ void __launch_bounds__(256)
gemm_mma_3(GemmPtrs p, int lda, int ldb, int ldc, int K)
{
    const int z = blockIdx.z;
    gemm_body<BN, WM, WN, true, false>(p.A[z], lda, p.B[z], ldb, p.C[z], ldc,
                                       nullptr, K, 1.f);
}

// strided-z variant
template <int BN, int WM, int WN, bool NMAJOR, bool RES>
__global__ void __launch_bounds__(256)
gemm_mma_z(const float* __restrict__ A, int lda, long long sAo, long long sAi,
           const float* __restrict__ B, int ldb, long long sBo, long long sBi,
           float* __restrict__ C, int ldc, long long sCo, long long sCi,
           const float* __restrict__ R, int K, float alpha, int zc)
{
    const int z  = blockIdx.z;
    const int zo = z / zc, zi = z % zc;
    gemm_body<BN, WM, WN, NMAJOR, RES>(
        A + zo * sAo + zi * sAi, lda,
        B + zo * sBo + zi * sBi, ldb,
        C + zo * sCo + zi * sCi, ldc,
        RES ? (R + zo * sCo + zi * sCi) : R,
        K, alpha);
}

// host-side smem size per config
static inline int gemm_smem(int BN, bool NMAJOR) {
    int abuf = 128 * 20 * 4;
    int bbuf = NMAJOR ? (16 * (BN + 4) * 4) : (BN * 20 * 4);
    return 3 * abuf + 3 * bbuf;
}

// ---------------- softmax over rows of 2048, in place (vectorized) ----------------
__global__ void __launch_bounds__(256)
softmax_rows_kernel(float* __restrict__ P)
{
    const int t = threadIdx.x;
    float4* row = reinterpret_cast<float4*>(P + (long long)blockIdx.x * SEQ);

    float4 a = row[t];
    float4 b = row[t + 256];
    float mx = fmaxf(fmaxf(fmaxf(a.x, a.y), fmaxf(a.z, a.w)),
                     fmaxf(fmaxf(b.x, b.y), fmaxf(b.z, b.w)));

    __shared__ float redm[8];
    __shared__ float reds[8];
    #pragma unroll
    for (int o = 16; o; o >>= 1) mx = fmaxf(mx, __shfl_xor_sync(0xffffffffu, mx, o));
    if ((t & 31) == 0) redm[t >> 5] = mx;
    __syncthreads();
    float bmax = redm[0];
    #pragma unroll
    for (int w = 1; w < 8; w++) bmax = fmaxf(bmax, redm[w]);

    a.x = __expf(a.x - bmax); a.y = __expf(a.y - bmax);
    a.z = __expf(a.z - bmax); a.w = __expf(a.w - bmax);
    b.x = __expf(b.x - bmax); b.y = __expf(b.y - bmax);
    b.z = __expf(b.z - bmax); b.w = __expf(b.w - bmax);
    float s = a.x + a.y + a.z + a.w + b.x + b.y + b.z + b.w;

    #pragma unroll
    for (int o = 16; o; o >>= 1) s += __shfl_xor_sync(0xffffffffu, s, o);
    if ((t & 31) == 0) reds[t >> 5] = s;
    __syncthreads();
    float bsum = 0.f;
    #pragma unroll
    for (int w = 0; w < 8; w++) bsum += reds[w];

    const float inv = 1.f / bsum;
    a.x *= inv; a.y *= inv; a.z *= inv; a.w *= inv;
    b.x *= inv; b.y *= inv; b.z *= inv; b.w *= inv;
    row[t] = a;
    row[t + 256] = b;
}

// ---------------- layernorm over rows of 1024 (vectorized) ----------------
__global__ void __launch_bounds__(256)
layernorm_kernel(const float* __restrict__ X,
                 const float* __restrict__ gamma,
                 const float* __restrict__ beta,
                 float* __restrict__ O)
{
    const int t = threadIdx.x;
    const float4* x = reinterpret_cast<const float4*>(X + (long long)blockIdx.x * DMODEL);
    float4* o = reinterpret_cast<float4*>(O + (long long)blockIdx.x * DMODEL);

    float4 v = x[t];
    float s = v.x + v.y + v.z + v.w;

    __shared__ float red1[8];
    __shared__ float red2[8];
    #pragma unroll
    for (int o2 = 16; o2; o2 >>= 1) s += __shfl_xor_sync(0xffffffffu, s, o2);
    if ((t & 31) == 0) red1[t >> 5] = s;
    __syncthreads();
    float tot = 0.f;
    #pragma unroll
    for (int w = 0; w < 8; w++) tot += red1[w];
    const float mean = tot * (1.f / DMODEL);

    float dx = v.x - mean, dy = v.y - mean, dz = v.z - mean, dw = v.w - mean;
    float sq = dx * dx + dy * dy + dz * dz + dw * dw;
    #pragma unroll
    for (int o2 = 16; o2; o2 >>= 1) sq += __shfl_xor_sync(0xffffffffu, sq, o2);
    if ((t & 31) == 0) red2[t >> 5] = sq;
    __syncthreads();
    float vtot = 0.f;
    #pragma unroll
    for (int w = 0; w < 8; w++) vtot += red2[w];
    const float rstd = rsqrtf(vtot * (1.f / DMODEL) + 1e-6f);

    float4 gm = reinterpret_cast<const float4*>(gamma)[t];
    float4 bt = reinterpret_cast<const float4*>(beta)[t];
    o[t] = make_float4(dx * rstd * gm.x + bt.x,
                       dy * rstd * gm.y + bt.y,
                       dz * rstd * gm.z + bt.z,
                       dw * rstd * gm.w + bt.w);
}

// ---------------- host launch ----------------
extern "C" void kernel_launch(void* const* d_in, const int* in_sizes, int n_in,
                              void* d_out, int out_size)
{
    (void)in_sizes; (void)n_in;
    const float* q    = (const float*)d_in[0];
    const float* k    = (const float*)d_in[1];
    const float* v    = (const float*)d_in[2];
    const float* wqu  = (const float*)d_in[3];
    const float* wqv  = (const float*)d_in[4];
    const float* wku  = (const float*)d_in[5];
    const float* wkv  = (const float*)d_in[6];
    const float* wvu  = (const float*)d_in[7];
    const float* wvv  = (const float*)d_in[8];
    const float* fcu  = (const float*)d_in[9];
    const float* fcv  = (const float*)d_in[10];
    const float* lng  = (const float*)d_in[11];
    const float* lnb  = (const float*)d_in[12];
    float* out = (float*)d_out;

    float *p_tmp, *p_qh, *p_kh, *p_vh, *p_ctx, *p_pre, *p_scratch;
    cudaGetSymbolAddress((void**)&p_tmp, g_tmp);
    cudaGetSymbolAddress((void**)&p_qh,  g_qh);
    cudaGetSymbolAddress((void**)&p_kh,  g_kh);
    cudaGetSymbolAddress((void**)&p_vh,  g_vh);
    cudaGetSymbolAddress((void**)&p_ctx, g_ctx);
    cudaGetSymbolAddress((void**)&p_pre, g_pre);
    cudaGetSymbolAddress((void**)&p_scratch, g_attn_scratch);

    float* attn = ((long long)out_size >= OUT_ELEMS + ATTN_ELEMS) ? (out + OUT_ELEMS)
                                                                  : p_scratch;

    const dim3 blk(256);
    const long long BH  = (long long)SEQ * DMODEL;
    const long long ATT = (long long)SEQ * SEQ;

    // big-tile configs (BM=128, BN=256, WM=64, WN=64)
    const int smN256 = gemm_smem(256, true);    // 3*(10240+16640) = 80640
    const int smS256 = gemm_smem(256, false);   // 3*(10240+20480) = 92160
    const int smN64  = gemm_smem(64,  true);    // 43776

    cudaFuncSetAttribute(gemm_mma_3<256, 64, 64>,
                         cudaFuncAttributeMaxDynamicSharedMemorySize, smN256);
    cudaFuncSetAttribute(gemm_mma_z<256, 64, 64, false, false>,
                         cudaFuncAttributeMaxDynamicSharedMemorySize, smS256);
    cudaFuncSetAttribute(gemm_mma_z<64, 32, 32, true, false>,
                         cudaFuncAttributeMaxDynamicSharedMemorySize, smN64);
    cudaFuncSetAttribute(gemm_mma_z<256, 64, 64, true, true>,
                         cudaFuncAttributeMaxDynamicSharedMemorySize, smN256);

    // ---- proj stage 1: {q,k,v} @ Wu -> tmp[z] (batched, grid z=3, N=256) ----
    GemmPtrs p1;
    p1.A[0] = q;   p1.A[1] = k;   p1.A[2] = v;
    p1.B[0] = wqu; p1.B[1] = wku; p1.B[2] = wvu;
    p1.C[0] = p_tmp;
    p1.C[1] = p_tmp + (long long)ROWS * RNK;
    p1.C[2] = p_tmp + 2LL * ROWS * RNK;
    gemm_mma_3<256, 64, 64><<<dim3(RNK / 256, ROWS / 128, 3), blk, smN256>>>(
        p1, DMODEL, RNK, RNK, DMODEL);

    // ---- proj stage 2: tmp[z] @ Wv -> {qh,kh,vh} (batched, N=1024) ----
    GemmPtrs p2;
    p2.A[0] = p1.C[0]; p2.A[1] = p1.C[1]; p2.A[2] = p1.C[2];
    p2.B[0] = wqv; p2.B[1] = wkv; p2.B[2] = wvv;
    p2.C[0] = p_qh; p2.C[1] = p_kh; p2.C[2] = p_vh;
    gemm_mma_3<256, 64, 64><<<dim3(DMODEL / 256, ROWS / 128, 3), blk, smN256>>>(
        p2, RNK, DMODEL, DMODEL, RNK);

    // ---- scores: attn[b,h] = (1/8) * Qh @ Kh^T  (N=2048) ----
    gemm_mma_z<256, 64, 64, false, false><<<dim3(SEQ / 256, SEQ / 128, ZBH), blk, smS256>>>(
        p_qh, DMODEL, BH, DKH,
        p_kh, DMODEL, BH, DKH,
        attn, SEQ, ATT * NHEAD, ATT,
        nullptr, DKH, 0.125f, NHEAD);

    // ---- softmax in place ----
    softmax_rows_kernel<<<(unsigned)(ZBH * SEQ), blk>>>(attn);

    // ---- ctx: ctx[b,h] = attn @ Vh  (N=64, small config) ----
    gemm_mma_z<64, 32, 32, true, false><<<dim3(1, SEQ / 128, ZBH), blk, smN64>>>(
        attn, SEQ, ATT * NHEAD, ATT,
        p_vh, DMODEL, BH, DKH,
        p_ctx, DMODEL, BH, DKH,
        nullptr, SEQ, 1.f, NHEAD);

    // ---- fc1: tmp = ctx @ fc_u  (BN=64 -> 256 CTAs) ----
    gemm_mma_z<64, 32, 32, true, false><<<dim3(RNK / 64, ROWS / 128, 1), blk, smN64>>>(
        p_ctx, DMODEL, 0, 0,  fcu, RNK, 0, 0,
        p_tmp, RNK, 0, 0,  nullptr, DMODEL, 1.f, 1);

    // ---- fc2: pre = tmp @ fc_v + residual(q)  (N=1024) ----
    gemm_mma_z<256, 64, 64, true, true><<<dim3(DMODEL / 256, ROWS / 128, 1), blk, smN256>>>(
        p_tmp, RNK, 0, 0,  fcv, DMODEL, 0, 0,
        p_pre, DMODEL, 0, 0,  q, RNK, 1.f, 1);

    // ---- layernorm -> out ----
    layernorm_kernel<<<ROWS, blk>>>(p_pre, lng, lnb, out);
}

// round 15
// speedup vs baseline: 1.0408x; 1.0408x over previous
#include <cuda_runtime.h>
#include <cstdint>
#include <math.h>

// ---------------- problem constants ----------------
#define DMODEL 1024
#define NHEAD  16
#define DKH    64
#define RNK    256
#define BATCH  4
#define SEQ    2048
#define ROWS   (BATCH * SEQ)                 // 8192
#define ZBH    (BATCH * NHEAD)               // 64
static const long long OUT_ELEMS  = (long long)ROWS * DMODEL;             // 8,388,608
static const long long ATTN_ELEMS = (long long)BATCH * NHEAD * SEQ * SEQ; // 268,435,456

// ---------------- static scratch ----------------
__device__ float g_tmp[ROWS * RNK * 3];      // low-rank intermediates (q,k,v batched)
__device__ float g_qh [ROWS * DMODEL];
__device__ float g_kh [ROWS * DMODEL];
__device__ float g_vh [ROWS * DMODEL];
__device__ float g_ctx[ROWS * DMODEL];
__device__ float g_pre[ROWS * DMODEL];
__device__ float g_attn_scratch[(size_t)BATCH * NHEAD * SEQ * SEQ];

// ---------------- PTX helpers ----------------
__device__ __forceinline__ uint32_t smem_u32(const void* p) {
    uint32_t a;
    asm("{ .reg .u64 t; cvta.to.shared.u64 t, %1; cvt.u32.u64 %0, t; }" : "=r"(a) : "l"(p));
    return a;
}
#define CP16(dst, src) \
    asm volatile("cp.async.cg.shared.global [%0], [%1], 16;" :: "r"(dst), "l"(src))
#define CP_COMMIT() asm volatile("cp.async.commit_group;")
#define CP_WAIT(N)  asm volatile("cp.async.wait_group %0;" :: "n"(N))

__device__ __forceinline__ void mma_tf32(float* c, const uint32_t* a, const uint32_t* b) {
    asm volatile("mma.sync.aligned.m16n8k8.row.col.f32.tf32.tf32.f32 "
                 "{%0,%1,%2,%3}, {%4,%5,%6,%7}, {%8,%9}, {%0,%1,%2,%3};"
                 : "+f"(c[0]), "+f"(c[1]), "+f"(c[2]), "+f"(c[3])
                 : "r"(a[0]), "r"(a[1]), "r"(a[2]), "r"(a[3]),
                   "r"(b[0]), "r"(b[1]));
}
// TF32 multiplicands use the top 19 bits of a b32 register; raw fp32 bits = truncation.
__device__ __forceinline__ uint32_t ftf(float x) { return __float_as_uint(x); }

// ---------------- GEMM body: 128 x BN x 16 tile, 8 warps, 3-stage cp.async ----------------
// C[M,N] = alpha * A[M,K] @ op(B) (+ R)
// NMAJOR=true : B is [K,N] row-major ; NMAJOR=false: B is [N,K] row-major (C = A@B^T)
template <int BN, int WM, int WN, bool NMAJOR, bool RES>
__device__ __forceinline__ void gemm_body(
    const float* __restrict__ A, int lda,
    const float* __restrict__ B, int ldb,
    float* __restrict__ C, int ldc,
    const float* __restrict__ R,
    int K, float alpha)
{
    constexpr int BM = 128;
    constexpr int BK = 16;
    constexpr int MT = WM / 16;
    constexpr int NT = WN / 8;
    constexpr int WCOLS = BN / WN;
    constexpr int ASTR = BK + 4;                 // 20 floats
    constexpr int BROWS = NMAJOR ? BK : BN;
    constexpr int BSTR  = NMAJOR ? (BN + 4) : (BK + 4);
    constexpr int ABUF = BM * ASTR;
    constexpr int BBUF = BROWS * BSTR;

    extern __shared__ float dyn[];
    float* Asb = dyn;                            // 3 * ABUF
    float* Bsb = dyn + 3 * ABUF;                 // 3 * BBUF

    const int row0 = blockIdx.y * BM;
    const int col0 = blockIdx.x * BN;
    const int tid = threadIdx.x;
    const int wid = tid >> 5;
    const int lid = tid & 31;
    const int g = lid >> 2;
    const int t = lid & 3;
    const int wr = wid / WCOLS;
    const int wc = wid % WCOLS;
    const int wm0 = wr * WM;
    const int wn0 = wc * WN;

    float acc[MT][NT][4];
    #pragma unroll
    for (int i = 0; i < MT; i++)
        #pragma unroll
        for (int j = 0; j < NT; j++)
            #pragma unroll
            for (int x = 0; x < 4; x++) acc[i][j][x] = 0.f;

    const int KT = K >> 4;

    auto load_tile = [&](int kt, int buf) {
        const int k0 = kt * BK;
        const uint32_t sa  = smem_u32(Asb + buf * ABUF);
        const uint32_t sbm = smem_u32(Bsb + buf * BBUF);
        #pragma unroll
        for (int i = 0; i < (BM * 4) / 256; i++) {
            int idx = tid + i * 256;
            int r = idx >> 2, s = idx & 3;
            CP16(sa + (uint32_t)(r * ASTR + s * 4) * 4,
                 A + (long long)(row0 + r) * lda + k0 + s * 4);
        }
        if constexpr (NMAJOR) {
            #pragma unroll
            for (int i = 0; i < (BK * BN / 4) / 256; i++) {
                int idx = tid + i * 256;
                int r = idx / (BN / 4), s = idx % (BN / 4);
                CP16(sbm + (uint32_t)(r * BSTR + s * 4) * 4,
                     B + (long long)(k0 + r) * ldb + col0 + s * 4);
            }
        } else {
            #pragma unroll
            for (int i = 0; i < (BN * 4) / 256; i++) {
                int idx = tid + i * 256;
                int r = idx >> 2, s = idx & 3;
                CP16(sbm + (uint32_t)(r * BSTR + s * 4) * 4,
                     B + (long long)(col0 + r) * ldb + k0 + s * 4);
            }
        }
        CP_COMMIT();
    };

    // 3-stage pipeline with constant pending-group count (empty commits at tail)
    load_tile(0, 0);
    if (KT > 1) load_tile(1, 1); else CP_COMMIT();

    int buf = 0;
    for (int kt = 0; kt < KT; kt++) {
        if (kt + 2 < KT) load_tile(kt + 2, (buf + 2) % 3); else CP_COMMIT();
        CP_WAIT(2);
        __syncthreads();

        const float* pa = Asb + buf * ABUF;
        const float* pb = Bsb + buf * BBUF;
        #pragma unroll
        for (int ks = 0; ks < 2; ks++) {
            uint32_t af[MT][4];
            uint32_t bf[NT][2];
            #pragma unroll
            for (int mi = 0; mi < MT; mi++) {
                int ar = wm0 + mi * 16 + g;
                int ac = ks * 8 + t;
                af[mi][0] = ftf(pa[ar * ASTR + ac]);
                af[mi][1] = ftf(pa[(ar + 8) * ASTR + ac]);
                af[mi][2] = ftf(pa[ar * ASTR + ac + 4]);
                af[mi][3] = ftf(pa[(ar + 8) * ASTR + ac + 4]);
            }
            #pragma unroll
            for (int ni = 0; ni < NT; ni++) {
                int bn = wn0 + ni * 8 + g;
                int bk = ks * 8 + t;
                if constexpr (NMAJOR) {
                    bf[ni][0] = ftf(pb[bk * BSTR + bn]);
                    bf[ni][1] = ftf(pb[(bk + 4) * BSTR + bn]);
                } else {
                    bf[ni][0] = ftf(pb[bn * BSTR + bk]);
                    bf[ni][1] = ftf(pb[bn * BSTR + bk + 4]);
                }
            }
            #pragma unroll
            for (int mi = 0; mi < MT; mi++)
                #pragma unroll
                for (int ni = 0; ni < NT; ni++)
                    mma_tf32(acc[mi][ni], af[mi], bf[ni]);
        }
        __syncthreads();
        buf = (buf + 1) % 3;
    }

    // ---- epilogue ----
    #pragma unroll
    for (int mi = 0; mi < MT; mi++) {
        #pragma unroll
        for (int ni = 0; ni < NT; ni++) {
            int r0 = row0 + wm0 + mi * 16 + g;
            int c0 = col0 + wn0 + ni * 8 + 2 * t;
            long long i0 = (long long)r0 * ldc + c0;
            long long i1 = i0 + 8LL * ldc;
            float v0 = acc[mi][ni][0] * alpha;
            float v1 = acc[mi][ni][1] * alpha;
            float v2 = acc[mi][ni][2] * alpha;
            float v3 = acc[mi][ni][3] * alpha;
            if constexpr (RES) {
                v0 += R[i0]; v1 += R[i0 + 1];
                v2 += R[i1]; v3 += R[i1 + 1];
            }
            *reinterpret_cast<float2*>(C + i0) = make_float2(v0, v1);
            *reinterpret_cast<float2*>(C + i1) = make_float2(v2, v3);
        }
    }
}

// ---------------- kernel wrappers ----------------
struct GemmPtrs {
    const float* A[3];
    const float* B[3];
    float*       C[3];
};

// batched-triple (q,k,v share shapes): z selects pointer set
template <int BN, int WM, int WN>
__global__ void __launch_bounds__(256, 2)
gemm_mma_3(GemmPtrs p, int lda, int ldb, int ldc, int K)
{
    const int z = blockIdx.z;
    gemm_body<BN, WM, WN, true, false>(p.A[z], lda, p.B[z], ldb, p.C[z], ldc,
                                       nullptr, K, 1.f);
}

// strided-z variant
template <int BN, int WM, int WN, bool NMAJOR, bool RES>
__global__ void __launch_bounds__(256, 2)
gemm_mma_z(const float* __restrict__ A, int lda, long long sAo, long long sAi,
           const float* __restrict__ B, int ldb, long long sBo, long long sBi,
           float* __restrict__ C, int ldc, long long sCo, long long sCi,
           const float* __restrict__ R, int K, float alpha, int zc)
{
    const int z  = blockIdx.z;
    const int zo = z / zc, zi = z % zc;
    gemm_body<BN, WM, WN, NMAJOR, RES>(
        A + zo * sAo + zi * sAi, lda,
        B + zo * sBo + zi * sBi, ldb,
        C + zo * sCo + zi * sCi, ldc,
        RES ? (R + zo * sCo + zi * sCi) : R,
        K, alpha);
}

// host-side smem size per config
static inline int gemm_smem(int BN, bool NMAJOR) {
    int abuf = 128 * 20 * 4;
    int bbuf = NMAJOR ? (16 * (BN + 4) * 4) : (BN * 20 * 4);
    return 3 * abuf + 3 * bbuf;
}

// ---------------- softmax over rows of 2048, in place (vectorized) ----------------
__global__ void __launch_bounds__(256)
softmax_rows_kernel(float* __restrict__ P)
{
    const int t = threadIdx.x;
    float4* row = reinterpret_cast<float4*>(P + (long long)blockIdx.x * SEQ);

    float4 a = row[t];
    float4 b = row[t + 256];
    float mx = fmaxf(fmaxf(fmaxf(a.x, a.y), fmaxf(a.z, a.w)),
                     fmaxf(fmaxf(b.x, b.y), fmaxf(b.z, b.w)));

    __shared__ float redm[8];
    __shared__ float reds[8];
    #pragma unroll
    for (int o = 16; o; o >>= 1) mx = fmaxf(mx, __shfl_xor_sync(0xffffffffu, mx, o));
    if ((t & 31) == 0) redm[t >> 5] = mx;
    __syncthreads();
    float bmax = redm[0];
    #pragma unroll
    for (int w = 1; w < 8; w++) bmax = fmaxf(bmax, redm[w]);

    a.x = __expf(a.x - bmax); a.y = __expf(a.y - bmax);
    a.z = __expf(a.z - bmax); a.w = __expf(a.w - bmax);
    b.x = __expf(b.x - bmax); b.y = __expf(b.y - bmax);
    b.z = __expf(b.z - bmax); b.w = __expf(b.w - bmax);
    float s = a.x + a.y + a.z + a.w + b.x + b.y + b.z + b.w;

    #pragma unroll
    for (int o = 16; o; o >>= 1) s += __shfl_xor_sync(0xffffffffu, s, o);
    if ((t & 31) == 0) reds[t >> 5] = s;
    __syncthreads();
    float bsum = 0.f;
    #pragma unroll
    for (int w = 0; w < 8; w++) bsum += reds[w];

    const float inv = 1.f / bsum;
    a.x *= inv; a.y *= inv; a.z *= inv; a.w *= inv;
    b.x *= inv; b.y *= inv; b.z *= inv; b.w *= inv;
    row[t] = a;
    row[t + 256] = b;
}

// ---------------- layernorm over rows of 1024 (vectorized) ----------------
__global__ void __launch_bounds__(256)
layernorm_kernel(const float* __restrict__ X,
                 const float* __restrict__ gamma,
                 const float* __restrict__ beta,
                 float* __restrict__ O)
{
    const int t = threadIdx.x;
    const float4* x = reinterpret_cast<const float4*>(X + (long long)blockIdx.x * DMODEL);
    float4* o = reinterpret_cast<float4*>(O + (long long)blockIdx.x * DMODEL);

    float4 v = x[t];
    float s = v.x + v.y + v.z + v.w;

    __shared__ float red1[8];
    __shared__ float red2[8];
    #pragma unroll
    for (int o2 = 16; o2; o2 >>= 1) s += __shfl_xor_sync(0xffffffffu, s, o2);
    if ((t & 31) == 0) red1[t >> 5] = s;
    __syncthreads();
    float tot = 0.f;
    #pragma unroll
    for (int w = 0; w < 8; w++) tot += red1[w];
    const float mean = tot * (1.f / DMODEL);

    float dx = v.x - mean, dy = v.y - mean, dz = v.z - mean, dw = v.w - mean;
    float sq = dx * dx + dy * dy + dz * dz + dw * dw;
    #pragma unroll
    for (int o2 = 16; o2; o2 >>= 1) sq += __shfl_xor_sync(0xffffffffu, sq, o2);
    if ((t & 31) == 0) red2[t >> 5] = sq;
    __syncthreads();
    float vtot = 0.f;
    #pragma unroll
    for (int w = 0; w < 8; w++) vtot += red2[w];
    const float rstd = rsqrtf(vtot * (1.f / DMODEL) + 1e-6f);

    float4 gm = reinterpret_cast<const float4*>(gamma)[t];
    float4 bt = reinterpret_cast<const float4*>(beta)[t];
    o[t] = make_float4(dx * rstd * gm.x + bt.x,
                       dy * rstd * gm.y + bt.y,
                       dz * rstd * gm.z + bt.z,
                       dw * rstd * gm.w + bt.w);
}

// ---------------- host launch ----------------
extern "C" void kernel_launch(void* const* d_in, const int* in_sizes, int n_in,
                              void* d_out, int out_size)
{
    (void)in_sizes; (void)n_in;
    const float* q    = (const float*)d_in[0];
    const float* k    = (const float*)d_in[1];
    const float* v    = (const float*)d_in[2];
    const float* wqu  = (const float*)d_in[3];
    const float* wqv  = (const float*)d_in[4];
    const float* wku  = (const float*)d_in[5];
    const float* wkv  = (const float*)d_in[6];
    const float* wvu  = (const float*)d_in[7];
    const float* wvv  = (const float*)d_in[8];
    const float* fcu  = (const float*)d_in[9];
    const float* fcv  = (const float*)d_in[10];
    const float* lng  = (const float*)d_in[11];
    const float* lnb  = (const float*)d_in[12];
    float* out = (float*)d_out;

    float *p_tmp, *p_qh, *p_kh, *p_vh, *p_ctx, *p_pre, *p_scratch;
    cudaGetSymbolAddress((void**)&p_tmp, g_tmp);
    cudaGetSymbolAddress((void**)&p_qh,  g_qh);
    cudaGetSymbolAddress((void**)&p_kh,  g_kh);
    cudaGetSymbolAddress((void**)&p_vh,  g_vh);
    cudaGetSymbolAddress((void**)&p_ctx, g_ctx);
    cudaGetSymbolAddress((void**)&p_pre, g_pre);
    cudaGetSymbolAddress((void**)&p_scratch, g_attn_scratch);

    float* attn = ((long long)out_size >= OUT_ELEMS + ATTN_ELEMS) ? (out + OUT_ELEMS)
                                                                  : p_scratch;

    const dim3 blk(256);
    const long long BH  = (long long)SEQ * DMODEL;
    const long long ATT = (long long)SEQ * SEQ;

    const int smN128 = gemm_smem(128, true);    // 56064
    const int smS128 = gemm_smem(128, false);   // 61440
    const int smN64  = gemm_smem(64,  true);    // 43776

    cudaFuncSetAttribute(gemm_mma_3<128, 64, 32>,
                         cudaFuncAttributeMaxDynamicSharedMemorySize, smN128);
    cudaFuncSetAttribute(gemm_mma_3<128, 64, 32>,
                         cudaFuncAttributePreferredSharedMemoryCarveout, 100);
    cudaFuncSetAttribute(gemm_mma_z<128, 64, 32, false, false>,
                         cudaFuncAttributeMaxDynamicSharedMemorySize, smS128);
    cudaFuncSetAttribute(gemm_mma_z<128, 64, 32, false, false>,
                         cudaFuncAttributePreferredSharedMemoryCarveout, 100);
    cudaFuncSetAttribute(gemm_mma_z<64, 32, 32, true, false>,
                         cudaFuncAttributeMaxDynamicSharedMemorySize, smN64);
    cudaFuncSetAttribute(gemm_mma_z<64, 32, 32, true, false>,
                         cudaFuncAttributePreferredSharedMemoryCarveout, 100);
    cudaFuncSetAttribute(gemm_mma_z<128, 64, 32, true, true>,
                         cudaFuncAttributeMaxDynamicSharedMemorySize, smN128);
    cudaFuncSetAttribute(gemm_mma_z<128, 64, 32, true, true>,
                         cudaFuncAttributePreferredSharedMemoryCarveout, 100);

    // ---- proj stage 1: {q,k,v} @ Wu -> tmp[z] (batched, grid z=3) ----
    GemmPtrs p1;
    p1.A[0] = q;   p1.A[1] = k;   p1.A[2] = v;
    p1.B[0] = wqu; p1.B[1] = wku; p1.B[2] = wvu;
    p1.C[0] = p_tmp;
    p1.C[1] = p_tmp + (long long)ROWS * RNK;
    p1.C[2] = p_tmp + 2LL * ROWS * RNK;
    gemm_mma_3<128, 64, 32><<<dim3(RNK / 128, ROWS / 128, 3), blk, smN128>>>(
        p1, DMODEL, RNK, RNK, DMODEL);

    // ---- proj stage 2: tmp[z] @ Wv -> {qh,kh,vh} (batched) ----
    GemmPtrs p2;
    p2.A[0] = p1.C[0]; p2.A[1] = p1.C[1]; p2.A[2] = p1.C[2];
    p2.B[0] = wqv; p2.B[1] = wkv; p2.B[2] = wvv;
    p2.C[0] = p_qh; p2.C[1] = p_kh; p2.C[2] = p_vh;
    gemm_mma_3<128, 64, 32><<<dim3(DMODEL / 128, ROWS / 128, 3), blk, smN128>>>(
        p2, RNK, DMODEL, DMODEL, RNK);

    // ---- scores: attn[b,h] = (1/8) * Qh @ Kh^T ----
    gemm_mma_z<128, 64, 32, false, false><<<dim3(SEQ / 128, SEQ / 128, ZBH), blk, smS128>>>(
        p_qh, DMODEL, BH, DKH,
        p_kh, DMODEL, BH, DKH,
        attn, SEQ, ATT * NHEAD, ATT,
        nullptr, DKH, 0.125f, NHEAD);

    // ---- softmax in place ----
    softmax_rows_kernel<<<(unsigned)(ZBH * SEQ), blk>>>(attn);

    // ---- ctx: ctx[b,h] = attn @ Vh ----
    gemm_mma_z<64, 32, 32, true, false><<<dim3(1, SEQ / 128, ZBH), blk, smN64>>>(
        attn, SEQ, ATT * NHEAD, ATT,
        p_vh, DMODEL, BH, DKH,
        p_ctx, DMODEL, BH, DKH,
        nullptr, SEQ, 1.f, NHEAD);

    // ---- fc1: tmp = ctx @ fc_u  (BN=64 -> 256 CTAs) ----
    gemm_mma_z<64, 32, 32, true, false><<<dim3(RNK / 64, ROWS / 128, 1), blk, smN64>>>(
        p_ctx, DMODEL, 0, 0,  fcu, RNK, 0, 0,
        p_tmp, RNK, 0, 0,  nullptr, DMODEL, 1.f, 1);

    // ---- fc2: pre = tmp @ fc_v + residual(q) ----
    gemm_mma_z<128, 64, 32, true, true><<<dim3(DMODEL / 128, ROWS / 128, 1), blk, smN128>>>(
        p_tmp, RNK, 0, 0,  fcv, DMODEL, 0, 0,
        p_pre, DMODEL, 0, 0,  q, RNK, 1.f, 1);

    // ---- layernorm -> out ----
    layernorm_kernel<<<ROWS, blk>>>(p_pre, lng, lnb, out);
}

// round 16
// speedup vs baseline: 1.1735x; 1.1276x over previous
#include <cuda_runtime.h>
#include <cstdint>
#include <math.h>

// ---------------- problem constants ----------------
#define DMODEL 1024
#define NHEAD  16
#define DKH    64
#define RNK    256
#define BATCH  4
#define SEQ    2048
#define ROWS   (BATCH * SEQ)                 // 8192
#define ZBH    (BATCH * NHEAD)               // 64
static const long long OUT_ELEMS  = (long long)ROWS * DMODEL;             // 8,388,608
static const long long ATTN_ELEMS = (long long)BATCH * NHEAD * SEQ * SEQ; // 268,435,456

// ---------------- static scratch ----------------
__device__ float g_tmp[ROWS * RNK * 3];      // low-rank intermediates (q,k,v batched)
__device__ float g_qh [ROWS * DMODEL];
__device__ float g_kh [ROWS * DMODEL];
__device__ float g_vh [ROWS * DMODEL];
__device__ float g_ctx[ROWS * DMODEL];
__device__ float g_pre[ROWS * DMODEL];
__device__ float g_attn_scratch[(size_t)BATCH * NHEAD * SEQ * SEQ];

// ---------------- PTX helpers ----------------
__device__ __forceinline__ uint32_t smem_u32(const void* p) {
    uint32_t a;
    asm("{ .reg .u64 t; cvta.to.shared.u64 t, %1; cvt.u32.u64 %0, t; }" : "=r"(a) : "l"(p));
    return a;
}
#define CP16(dst, src) \
    asm volatile("cp.async.cg.shared.global [%0], [%1], 16;" :: "r"(dst), "l"(src))
#define CP_COMMIT() asm volatile("cp.async.commit_group;")
#define CP_WAIT(N)  asm volatile("cp.async.wait_group %0;" :: "n"(N))

__device__ __forceinline__ void mma_tf32(float* c, const uint32_t* a, const uint32_t* b) {
    asm volatile("mma.sync.aligned.m16n8k8.row.col.f32.tf32.tf32.f32 "
                 "{%0,%1,%2,%3}, {%4,%5,%6,%7}, {%8,%9}, {%0,%1,%2,%3};"
                 : "+f"(c[0]), "+f"(c[1]), "+f"(c[2]), "+f"(c[3])
                 : "r"(a[0]), "r"(a[1]), "r"(a[2]), "r"(a[3]),
                   "r"(b[0]), "r"(b[1]));
}
// TF32 multiplicands use the top 19 bits of a b32 register; raw fp32 bits = truncation.
__device__ __forceinline__ uint32_t ftf(float x) { return __float_as_uint(x); }

// ---------------- GEMM body: 128 x BN x 32 tile, 8 warps, 2-stage cp.async ----------------
// C[M,N] = alpha * A[M,K] @ B[K,N] (+ R), B row-major [K,N].
template <int BN, int WM, int WN, bool RES>
__device__ __forceinline__ void gemm_body32(
    const float* __restrict__ A, int lda,
    const float* __restrict__ B, int ldb,
    float* __restrict__ C, int ldc,
    const float* __restrict__ R,
    int K, float alpha)
{
    constexpr int BM = 128;
    constexpr int BK = 32;
    constexpr int MT = WM / 16;
    constexpr int NT = WN / 8;
    constexpr int WCOLS = BN / WN;
    constexpr int ASTR = BK + 4;                 // 36 floats
    constexpr int BSTR = BN + 4;
    constexpr int ABUF = BM * ASTR;
    constexpr int BBUF = BK * BSTR;

    extern __shared__ float dyn[];
    float* Asb = dyn;                            // 2 * ABUF
    float* Bsb = dyn + 2 * ABUF;                 // 2 * BBUF

    const int row0 = blockIdx.y * BM;
    const int col0 = blockIdx.x * BN;
    const int tid = threadIdx.x;
    const int wid = tid >> 5;
    const int lid = tid & 31;
    const int g = lid >> 2;
    const int t = lid & 3;
    const int wr = wid / WCOLS;
    const int wc = wid % WCOLS;
    const int wm0 = wr * WM;
    const int wn0 = wc * WN;

    float acc[MT][NT][4];
    #pragma unroll
    for (int i = 0; i < MT; i++)
        #pragma unroll
        for (int j = 0; j < NT; j++)
            #pragma unroll
            for (int x = 0; x < 4; x++) acc[i][j][x] = 0.f;

    const int KT = K >> 5;                       // 32-wide K tiles

    auto load_tile = [&](int kt, int buf) {
        const int k0 = kt * BK;
        const uint32_t sa  = smem_u32(Asb + buf * ABUF);
        const uint32_t sbm = smem_u32(Bsb + buf * BBUF);
        // A: 128 rows x 32 floats = 1024 cp16 -> 4/thread
        #pragma unroll
        for (int i = 0; i < 4; i++) {
            int idx = tid + i * 256;
            int r = idx >> 3, s = idx & 7;
            CP16(sa + (uint32_t)(r * ASTR + s * 4) * 4,
                 A + (long long)(row0 + r) * lda + k0 + s * 4);
        }
        // B: 32 rows x BN floats = 32*BN/4 cp16 -> BN/32 per thread
        #pragma unroll
        for (int i = 0; i < BN / 32; i++) {
            int idx = tid + i * 256;
            int r = idx / (BN / 4), s = idx % (BN / 4);
            CP16(sbm + (uint32_t)(r * BSTR + s * 4) * 4,
                 B + (long long)(k0 + r) * ldb + col0 + s * 4);
        }
        CP_COMMIT();
    };

    load_tile(0, 0);

    for (int kt = 0; kt < KT; kt++) {
        const int buf = kt & 1;
        if (kt + 1 < KT) {
            load_tile(kt + 1, buf ^ 1);
            CP_WAIT(1);
        } else {
            CP_WAIT(0);
        }
        __syncthreads();

        const float* pa = Asb + buf * ABUF;
        const float* pb = Bsb + buf * BBUF;
        #pragma unroll
        for (int ks = 0; ks < 4; ks++) {
            uint32_t af[MT][4];
            uint32_t bf[NT][2];
            #pragma unroll
            for (int mi = 0; mi < MT; mi++) {
                int ar = wm0 + mi * 16 + g;
                int ac = ks * 8 + t;
                af[mi][0] = ftf(pa[ar * ASTR + ac]);
                af[mi][1] = ftf(pa[(ar + 8) * ASTR + ac]);
                af[mi][2] = ftf(pa[ar * ASTR + ac + 4]);
                af[mi][3] = ftf(pa[(ar + 8) * ASTR + ac + 4]);
            }
            #pragma unroll
            for (int ni = 0; ni < NT; ni++) {
                int bn = wn0 + ni * 8 + g;
                int bk = ks * 8 + t;
                bf[ni][0] = ftf(pb[bk * BSTR + bn]);
                bf[ni][1] = ftf(pb[(bk + 4) * BSTR + bn]);
            }
            #pragma unroll
            for (int mi = 0; mi < MT; mi++)
                #pragma unroll
                for (int ni = 0; ni < NT; ni++)
                    mma_tf32(acc[mi][ni], af[mi], bf[ni]);
        }
        __syncthreads();
    }

    // ---- epilogue ----
    #pragma unroll
    for (int mi = 0; mi < MT; mi++) {
        #pragma unroll
        for (int ni = 0; ni < NT; ni++) {
            int r0 = row0 + wm0 + mi * 16 + g;
            int c0 = col0 + wn0 + ni * 8 + 2 * t;
            long long i0 = (long long)r0 * ldc + c0;
            long long i1 = i0 + 8LL * ldc;
            float v0 = acc[mi][ni][0] * alpha;
            float v1 = acc[mi][ni][1] * alpha;
            float v2 = acc[mi][ni][2] * alpha;
            float v3 = acc[mi][ni][3] * alpha;
            if constexpr (RES) {
                v0 += R[i0]; v1 += R[i0 + 1];
                v2 += R[i1]; v3 += R[i1 + 1];
            }
            *reinterpret_cast<float2*>(C + i0) = make_float2(v0, v1);
            *reinterpret_cast<float2*>(C + i1) = make_float2(v2, v3);
        }
    }
}

// ---------------- kernel wrappers ----------------
struct GemmPtrs {
    const float* A[3];
    const float* B[3];
    float*       C[3];
};

// batched-triple (q,k,v share shapes): z selects pointer set
template <int BN, int WM, int WN>
__global__ void __launch_bounds__(256)
gemm_mma_3(GemmPtrs p, int lda, int ldb, int ldc, int K)
{
    const int z = blockIdx.z;
    gemm_body32<BN, WM, WN, false>(p.A[z], lda, p.B[z], ldb, p.C[z], ldc,
                                   nullptr, K, 1.f);
}

// strided-z variant
template <int BN, int WM, int WN, bool RES>
__global__ void __launch_bounds__(256)
gemm_mma_z(const float* __restrict__ A, int lda, long long sAo, long long sAi,
           const float* __restrict__ B, int ldb, long long sBo, long long sBi,
           float* __restrict__ C, int ldc, long long sCo, long long sCi,
           const float* __restrict__ R, int K, float alpha, int zc)
{
    const int z  = blockIdx.z;
    const int zo = z / zc, zi = z % zc;
    gemm_body32<BN, WM, WN, RES>(
        A + zo * sAo + zi * sAi, lda,
        B + zo * sBo + zi * sBi, ldb,
        C + zo * sCo + zi * sCi, ldc,
        RES ? (R + zo * sCo + zi * sCi) : R,
        K, alpha);
}

static inline int gemm_smem32(int BN) {
    return 2 * 128 * 36 * 4 + 2 * 32 * (BN + 4) * 4;
}

// ---------------- scores kernel: single-shot 128x128, K=64 ----------------
// attn[z][row, col] = alpha * Qh[row,:] . Kh[col,:]   (both [S, 64] slices)
__global__ void __launch_bounds__(256)
scores_kernel(const float* __restrict__ Q, long long sQo, long long sQi,
              const float* __restrict__ Kh, long long sKo, long long sKi,
              float* __restrict__ P, long long sPo, long long sPi,
              float alpha, int zc)
{
    constexpr int ASTR = 68;                     // 64 + 4 pad
    __shared__ float Qs[128 * ASTR];
    __shared__ float Ks[128 * ASTR];

    const int z  = blockIdx.z;
    const int zo = z / zc, zi = z % zc;
    Q  += zo * sQo + zi * sQi;
    Kh += zo * sKo + zi * sKi;
    P  += zo * sPo + zi * sPi;

    const int row0 = blockIdx.y * 128;
    const int col0 = blockIdx.x * 128;
    const int tid = threadIdx.x;
    const int wid = tid >> 5;
    const int lid = tid & 31;
    const int g = lid >> 2;
    const int t = lid & 3;
    const int wr = wid >> 1;                     // 0..3  (WM=32)
    const int wc = wid & 1;                      // 0..1  (WN=64)
    const int wm0 = wr * 32;
    const int wn0 = wc * 64;

    const uint32_t sq = smem_u32(Qs);
    const uint32_t sk = smem_u32(Ks);

    // load Q block 128x64 and K block 128x64 (lda = DMODEL)
    #pragma unroll
    for (int i = 0; i < 8; i++) {
        int idx = tid + i * 256;                 // 2048 cp16
        int r = idx >> 4, s = idx & 15;
        CP16(sq + (uint32_t)(r * ASTR + s * 4) * 4,
             Q + (long long)(row0 + r) * DMODEL + s * 4);
    }
    #pragma unroll
    for (int i = 0; i < 8; i++) {
        int idx = tid + i * 256;
        int r = idx >> 4, s = idx & 15;
        CP16(sk + (uint32_t)(r * ASTR + s * 4) * 4,
             Kh + (long long)(col0 + r) * DMODEL + s * 4);
    }
    CP_COMMIT();
    CP_WAIT(0);
    __syncthreads();

    float acc[2][8][4];
    #pragma unroll
    for (int i = 0; i < 2; i++)
        #pragma unroll
        for (int j = 0; j < 8; j++)
            #pragma unroll
            for (int x = 0; x < 4; x++) acc[i][j][x] = 0.f;

    #pragma unroll
    for (int ks = 0; ks < 8; ks++) {
        uint32_t af[2][4];
        uint32_t bf[8][2];
        #pragma unroll
        for (int mi = 0; mi < 2; mi++) {
            int ar = wm0 + mi * 16 + g;
            int ac = ks * 8 + t;
            af[mi][0] = ftf(Qs[ar * ASTR + ac]);
            af[mi][1] = ftf(Qs[(ar + 8) * ASTR + ac]);
            af[mi][2] = ftf(Qs[ar * ASTR + ac + 4]);
            af[mi][3] = ftf(Qs[(ar + 8) * ASTR + ac + 4]);
        }
        #pragma unroll
        for (int ni = 0; ni < 8; ni++) {
            int bn = wn0 + ni * 8 + g;
            int bk = ks * 8 + t;
            bf[ni][0] = ftf(Ks[bn * ASTR + bk]);
            bf[ni][1] = ftf(Ks[bn * ASTR + bk + 4]);
        }
        #pragma unroll
        for (int mi = 0; mi < 2; mi++)
            #pragma unroll
            for (int ni = 0; ni < 8; ni++)
                mma_tf32(acc[mi][ni], af[mi], bf[ni]);
    }

    #pragma unroll
    for (int mi = 0; mi < 2; mi++) {
        #pragma unroll
        for (int ni = 0; ni < 8; ni++) {
            int r0 = row0 + wm0 + mi * 16 + g;
            int c0 = col0 + wn0 + ni * 8 + 2 * t;
            long long i0 = (long long)r0 * SEQ + c0;
            long long i1 = i0 + 8LL * SEQ;
            *reinterpret_cast<float2*>(P + i0) =
                make_float2(acc[mi][ni][0] * alpha, acc[mi][ni][1] * alpha);
            *reinterpret_cast<float2*>(P + i1) =
                make_float2(acc[mi][ni][2] * alpha, acc[mi][ni][3] * alpha);
        }
    }
}

// ---------------- softmax over rows of 2048, in place (vectorized) ----------------
__global__ void __launch_bounds__(256)
softmax_rows_kernel(float* __restrict__ P)
{
    const int t = threadIdx.x;
    float4* row = reinterpret_cast<float4*>(P + (long long)blockIdx.x * SEQ);

    float4 a = row[t];
    float4 b = row[t + 256];
    float mx = fmaxf(fmaxf(fmaxf(a.x, a.y), fmaxf(a.z, a.w)),
                     fmaxf(fmaxf(b.x, b.y), fmaxf(b.z, b.w)));

    __shared__ float redm[8];
    __shared__ float reds[8];
    #pragma unroll
    for (int o = 16; o; o >>= 1) mx = fmaxf(mx, __shfl_xor_sync(0xffffffffu, mx, o));
    if ((t & 31) == 0) redm[t >> 5] = mx;
    __syncthreads();
    float bmax = redm[0];
    #pragma unroll
    for (int w = 1; w < 8; w++) bmax = fmaxf(bmax, redm[w]);

    a.x = __expf(a.x - bmax); a.y = __expf(a.y - bmax);
    a.z = __expf(a.z - bmax); a.w = __expf(a.w - bmax);
    b.x = __expf(b.x - bmax); b.y = __expf(b.y - bmax);
    b.z = __expf(b.z - bmax); b.w = __expf(b.w - bmax);
    float s = a.x + a.y + a.z + a.w + b.x + b.y + b.z + b.w;

    #pragma unroll
    for (int o = 16; o; o >>= 1) s += __shfl_xor_sync(0xffffffffu, s, o);
    if ((t & 31) == 0) reds[t >> 5] = s;
    __syncthreads();
    float bsum = 0.f;
    #pragma unroll
    for (int w = 0; w < 8; w++) bsum += reds[w];

    const float inv = 1.f / bsum;
    a.x *= inv; a.y *= inv; a.z *= inv; a.w *= inv;
    b.x *= inv; b.y *= inv; b.z *= inv; b.w *= inv;
    row[t] = a;
    row[t + 256] = b;
}

// ---------------- layernorm over rows of 1024 (vectorized) ----------------
__global__ void __launch_bounds__(256)
layernorm_kernel(const float* __restrict__ X,
                 const float* __restrict__ gamma,
                 const float* __restrict__ beta,
                 float* __restrict__ O)
{
    const int t = threadIdx.x;
    const float4* x = reinterpret_cast<const float4*>(X + (long long)blockIdx.x * DMODEL);
    float4* o = reinterpret_cast<float4*>(O + (long long)blockIdx.x * DMODEL);

    float4 v = x[t];
    float s = v.x + v.y + v.z + v.w;

    __shared__ float red1[8];
    __shared__ float red2[8];
    #pragma unroll
    for (int o2 = 16; o2; o2 >>= 1) s += __shfl_xor_sync(0xffffffffu, s, o2);
    if ((t & 31) == 0) red1[t >> 5] = s;
    __syncthreads();
    float tot = 0.f;
    #pragma unroll
    for (int w = 0; w < 8; w++) tot += red1[w];
    const float mean = tot * (1.f / DMODEL);

    float dx = v.x - mean, dy = v.y - mean, dz = v.z - mean, dw = v.w - mean;
    float sq = dx * dx + dy * dy + dz * dz + dw * dw;
    #pragma unroll
    for (int o2 = 16; o2; o2 >>= 1) sq += __shfl_xor_sync(0xffffffffu, sq, o2);
    if ((t & 31) == 0) red2[t >> 5] = sq;
    __syncthreads();
    float vtot = 0.f;
    #pragma unroll
    for (int w = 0; w < 8; w++) vtot += red2[w];
    const float rstd = rsqrtf(vtot * (1.f / DMODEL) + 1e-6f);

    float4 gm = reinterpret_cast<const float4*>(gamma)[t];
    float4 bt = reinterpret_cast<const float4*>(beta)[t];
    o[t] = make_float4(dx * rstd * gm.x + bt.x,
                       dy * rstd * gm.y + bt.y,
                       dz * rstd * gm.z + bt.z,
                       dw * rstd * gm.w + bt.w);
}

// ---------------- host launch ----------------
extern "C" void kernel_launch(void* const* d_in, const int* in_sizes, int n_in,
                              void* d_out, int out_size)
{
    (void)in_sizes; (void)n_in;
    const float* q    = (const float*)d_in[0];
    const float* k    = (const float*)d_in[1];
    const float* v    = (const float*)d_in[2];
    const float* wqu  = (const float*)d_in[3];
    const float* wqv  = (const float*)d_in[4];
    const float* wku  = (const float*)d_in[5];
    const float* wkv  = (const float*)d_in[6];
    const float* wvu  = (const float*)d_in[7];
    const float* wvv  = (const float*)d_in[8];
    const float* fcu  = (const float*)d_in[9];
    const float* fcv  = (const float*)d_in[10];
    const float* lng  = (const float*)d_in[11];
    const float* lnb  = (const float*)d_in[12];
    float* out = (float*)d_out;

    float *p_tmp, *p_qh, *p_kh, *p_vh, *p_ctx, *p_pre, *p_scratch;
    cudaGetSymbolAddress((void**)&p_tmp, g_tmp);
    cudaGetSymbolAddress((void**)&p_qh,  g_qh);
    cudaGetSymbolAddress((void**)&p_kh,  g_kh);
    cudaGetSymbolAddress((void**)&p_vh,  g_vh);
    cudaGetSymbolAddress((void**)&p_ctx, g_ctx);
    cudaGetSymbolAddress((void**)&p_pre, g_pre);
    cudaGetSymbolAddress((void**)&p_scratch, g_attn_scratch);

    float* attn = ((long long)out_size >= OUT_ELEMS + ATTN_ELEMS) ? (out + OUT_ELEMS)
                                                                  : p_scratch;

    const dim3 blk(256);
    const long long BH  = (long long)SEQ * DMODEL;
    const long long ATT = (long long)SEQ * SEQ;

    const int sm128 = gemm_smem32(128);          // 70656
    const int sm64  = gemm_smem32(64);           // 54272

    cudaFuncSetAttribute(gemm_mma_3<128, 64, 32>,
                         cudaFuncAttributeMaxDynamicSharedMemorySize, sm128);
    cudaFuncSetAttribute(gemm_mma_z<64, 32, 32, false>,
                         cudaFuncAttributeMaxDynamicSharedMemorySize, sm64);
    cudaFuncSetAttribute(gemm_mma_z<128, 64, 32, true>,
                         cudaFuncAttributeMaxDynamicSharedMemorySize, sm128);

    // ---- proj stage 1: {q,k,v} @ Wu -> tmp[z] (batched, grid z=3) ----
    GemmPtrs p1;
    p1.A[0] = q;   p1.A[1] = k;   p1.A[2] = v;
    p1.B[0] = wqu; p1.B[1] = wku; p1.B[2] = wvu;
    p1.C[0] = p_tmp;
    p1.C[1] = p_tmp + (long long)ROWS * RNK;
    p1.C[2] = p_tmp + 2LL * ROWS * RNK;
    gemm_mma_3<128, 64, 32><<<dim3(RNK / 128, ROWS / 128, 3), blk, sm128>>>(
        p1, DMODEL, RNK, RNK, DMODEL);

    // ---- proj stage 2: tmp[z] @ Wv -> {qh,kh,vh} (batched) ----
    GemmPtrs p2;
    p2.A[0] = p1.C[0]; p2.A[1] = p1.C[1]; p2.A[2] = p1.C[2];
    p2.B[0] = wqv; p2.B[1] = wkv; p2.B[2] = wvv;
    p2.C[0] = p_qh; p2.C[1] = p_kh; p2.C[2] = p_vh;
    gemm_mma_3<128, 64, 32><<<dim3(DMODEL / 128, ROWS / 128, 3), blk, sm128>>>(
        p2, RNK, DMODEL, DMODEL, RNK);

    // ---- scores: attn[b,h] = (1/8) * Qh @ Kh^T  (single-shot K=64) ----
    scores_kernel<<<dim3(SEQ / 128, SEQ / 128, ZBH), blk>>>(
        p_qh, BH, DKH,
        p_kh, BH, DKH,
        attn, ATT * NHEAD, ATT,
        0.125f, NHEAD);

    // ---- softmax in place ----
    softmax_rows_kernel<<<(unsigned)(ZBH * SEQ), blk>>>(attn);

    // ---- ctx: ctx[b,h] = attn @ Vh ----
    gemm_mma_z<64, 32, 32, false><<<dim3(1, SEQ / 128, ZBH), blk, sm64>>>(
        attn, SEQ, ATT * NHEAD, ATT,
        p_vh, DMODEL, BH, DKH,
        p_ctx, DMODEL, BH, DKH,
        nullptr, SEQ, 1.f, NHEAD);

    // ---- fc1: tmp = ctx @ fc_u  (BN=64 -> 256 CTAs) ----
    gemm_mma_z<64, 32, 32, false><<<dim3(RNK / 64, ROWS / 128, 1), blk, sm64>>>(
        p_ctx, DMODEL, 0, 0,  fcu, RNK, 0, 0,
        p_tmp, RNK, 0, 0,  nullptr, DMODEL, 1.f, 1);

    // ---- fc2: pre = tmp @ fc_v + residual(q) ----
    gemm_mma_z<128, 64, 32, true><<<dim3(DMODEL / 128, ROWS / 128, 1), blk, sm128>>>(
        p_tmp, RNK, 0, 0,  fcv, DMODEL, 0, 0,
        p_pre, DMODEL, 0, 0,  q, RNK, 1.f, 1);

    // ---- layernorm -> out ----
    layernorm_kernel<<<ROWS, blk>>>(p_pre, lng, lnb, out);
}